// round 4
// baseline (speedup 1.0000x reference)
#include <cuda_runtime.h>
#include <cstdint>

#define N_NODES 100000
#define NE_MAX  1700032
#define SCAN_B  1024
#define NUM_SB  ((N_NODES + SCAN_B - 1) / SCAN_B)   // 98

// ---------------- scratch (alloc-free rule: __device__ globals) ----------------
__device__ int   g_deg   [N_NODES];
__device__ float g_dinv  [N_NODES];
__device__ int   g_rowptr[N_NODES + 1];
__device__ int   g_cursor[N_NODES];
__device__ int   g_bsum  [128];
__device__ __align__(16) int2  g_edge[NE_MAX];     // {col, w_bits} interleaved
__device__ __align__(16) float g_XW1[(size_t)N_NODES * 128];
__device__ __align__(16) float g_HW2[(size_t)N_NODES * 64];

// ---------------- small helpers ----------------
__device__ __forceinline__ float tf32_rnd(float x) {
    float r;
    asm("cvt.rna.tf32.f32 %0, %1;" : "=f"(r) : "f"(x));
    return r;
}

__device__ __forceinline__ void mma_tf32(float c[4], const float a[4], const float b[2]) {
    asm volatile(
        "mma.sync.aligned.m16n8k8.row.col.f32.tf32.tf32.f32 "
        "{%0,%1,%2,%3}, {%4,%5,%6,%7}, {%8,%9}, {%0,%1,%2,%3};"
        : "+f"(c[0]), "+f"(c[1]), "+f"(c[2]), "+f"(c[3])
        : "r"(__float_as_uint(a[0])), "r"(__float_as_uint(a[1])),
          "r"(__float_as_uint(a[2])), "r"(__float_as_uint(a[3])),
          "r"(__float_as_uint(b[0])), "r"(__float_as_uint(b[1])));
}

__device__ __forceinline__ void cp_async16(void* smem_dst, const void* gsrc, bool valid) {
    uint32_t d = (uint32_t)__cvta_generic_to_shared(smem_dst);
    int sz = valid ? 16 : 0;
    asm volatile("cp.async.cg.shared.global [%0], [%1], 16, %2;"
                 :: "r"(d), "l"(gsrc), "r"(sz) : "memory");
}

// ---------------- CSR build ----------------
__global__ void zero_deg_kernel() {
    int i = blockIdx.x * blockDim.x + threadIdx.x;
    if (i < N_NODES) g_deg[i] = 0;
}

__global__ void deg_kernel(const int* __restrict__ rows, int nE4, int nE) {
    int i = blockIdx.x * blockDim.x + threadIdx.x;
    if (i < nE4) {
        int4 r = ((const int4*)rows)[i];
        atomicAdd(&g_deg[r.x], 1);
        atomicAdd(&g_deg[r.y], 1);
        atomicAdd(&g_deg[r.z], 1);
        atomicAdd(&g_deg[r.w], 1);
    } else {
        int j = nE4 * 4 + (i - nE4);
        if (j < nE) atomicAdd(&g_deg[rows[j]], 1);
    }
}

__global__ void dinv_kernel() {
    int i = blockIdx.x * blockDim.x + threadIdx.x;
    if (i < N_NODES) g_dinv[i] = rsqrtf((float)max(g_deg[i], 1));
}

__global__ __launch_bounds__(SCAN_B) void scanA_kernel() {
    __shared__ int s[SCAN_B];
    int tid = threadIdx.x;
    int i = blockIdx.x * SCAN_B + tid;
    int v = (i < N_NODES) ? g_deg[i] : 0;
    s[tid] = v;
    __syncthreads();
#pragma unroll
    for (int off = 1; off < SCAN_B; off <<= 1) {
        int t = (tid >= off) ? s[tid - off] : 0;
        __syncthreads();
        s[tid] += t;
        __syncthreads();
    }
    if (i < N_NODES) g_rowptr[i] = s[tid] - v;
    if (tid == SCAN_B - 1) g_bsum[blockIdx.x] = s[tid];
}

__global__ void scanB_kernel(int nb) {
    __shared__ int s[128];
    int tid = threadIdx.x;
    int v = (tid < nb) ? g_bsum[tid] : 0;
    s[tid] = v;
    __syncthreads();
#pragma unroll
    for (int off = 1; off < 128; off <<= 1) {
        int t = (tid >= off) ? s[tid - off] : 0;
        __syncthreads();
        s[tid] += t;
        __syncthreads();
    }
    if (tid < nb) g_bsum[tid] = s[tid] - v;
}

__global__ __launch_bounds__(SCAN_B) void scanC_kernel(int nE) {
    int i = blockIdx.x * SCAN_B + threadIdx.x;
    if (i < N_NODES) {
        int rp = g_rowptr[i] + g_bsum[blockIdx.x];
        g_rowptr[i] = rp;
        g_cursor[i] = rp;
    }
    if (i == 0) g_rowptr[N_NODES] = nE;
}

__device__ __forceinline__ void scatter_one(int r, int c) {
    int pos = atomicAdd(&g_cursor[r], 1);
    float w = g_dinv[r] * g_dinv[c];
    g_edge[pos] = make_int2(c, __float_as_int(w));
}

__global__ void scatter_kernel(const int* __restrict__ rows, const int* __restrict__ cols,
                               int nE4, int nE) {
    int i = blockIdx.x * blockDim.x + threadIdx.x;
    if (i < nE4) {
        int4 r = ((const int4*)rows)[i];
        int4 c = ((const int4*)cols)[i];
        scatter_one(r.x, c.x);
        scatter_one(r.y, c.y);
        scatter_one(r.z, c.z);
        scatter_one(r.w, c.w);
    } else {
        int j = nE4 * 4 + (i - nE4);
        if (j < nE) scatter_one(rows[j], cols[j]);
    }
}

// ---------------- TF32 tensor-core GEMM (3xTF32): C = A @ B ----------------
template <int BN>
__global__ __launch_bounds__(256)
void mma_gemm_kernel(int M, int N, int K,
                     const float* __restrict__ A,
                     const float* __restrict__ B,
                     float* __restrict__ C) {
    constexpr int BM = 128;
    constexpr int BK = 32;
    constexpr int AS = 36;
    constexpr int BS = BN + 8;
    constexpr int A_STAGE = BM * AS;
    constexpr int B_STAGE = BK * BS;
    constexpr int STAGE   = A_STAGE + B_STAGE;
    constexpr int WN = BN / 2;
    constexpr int NT = WN / 8;
    constexpr int B_LD = (BK * BN / 4) / 256;

    extern __shared__ float smem[];

    const int tid    = threadIdx.x;
    const int lane   = tid & 31;
    const int wid    = tid >> 5;
    const int warp_m = wid & 3;
    const int warp_n = wid >> 2;
    const int g      = lane >> 2;
    const int q      = lane & 3;
    const int rowBase = blockIdx.y * BM;
    const int colBase = blockIdx.x * BN;

    float acc[2][NT][4];
#pragma unroll
    for (int mt = 0; mt < 2; mt++)
#pragma unroll
        for (int nt = 0; nt < NT; nt++)
#pragma unroll
            for (int r = 0; r < 4; r++) acc[mt][nt][r] = 0.f;

    const int NITER = K / BK;

    auto load_tile = [&](int stage, int k0) {
        float* sA = smem + stage * STAGE;
        float* sB = sA + A_STAGE;
#pragma unroll
        for (int i = 0; i < 4; i++) {
            int e = tid + i * 256;
            int r = e >> 3;
            int c4 = (e & 7) * 4;
            int gr = rowBase + r;
            cp_async16(sA + r * AS + c4, A + (size_t)gr * K + k0 + c4, gr < M);
        }
#pragma unroll
        for (int i = 0; i < B_LD; i++) {
            int e = tid + i * 256;
            int r = e / (BN / 4);
            int c4 = (e % (BN / 4)) * 4;
            cp_async16(sB + r * BS + c4, B + (size_t)(k0 + r) * N + colBase + c4, true);
        }
        asm volatile("cp.async.commit_group;" ::: "memory");
    };

    load_tile(0, 0);

    for (int it = 0; it < NITER; ++it) {
        int cur = it & 1;
        if (it + 1 < NITER) {
            load_tile(cur ^ 1, (it + 1) * BK);
            asm volatile("cp.async.wait_group 1;" ::: "memory");
        } else {
            asm volatile("cp.async.wait_group 0;" ::: "memory");
        }
        __syncthreads();

        const float* sA = smem + cur * STAGE;
        const float* sB = sA + A_STAGE;

#pragma unroll
        for (int ks = 0; ks < 4; ks++) {
            float ah[2][4], al[2][4];
#pragma unroll
            for (int mt = 0; mt < 2; mt++) {
                const float* ap = sA + (warp_m * 32 + mt * 16 + g) * AS + ks * 8 + q;
                float a0 = ap[0];
                float a1 = ap[8 * AS];
                float a2 = ap[4];
                float a3 = ap[8 * AS + 4];
                ah[mt][0] = tf32_rnd(a0); al[mt][0] = tf32_rnd(a0 - ah[mt][0]);
                ah[mt][1] = tf32_rnd(a1); al[mt][1] = tf32_rnd(a1 - ah[mt][1]);
                ah[mt][2] = tf32_rnd(a2); al[mt][2] = tf32_rnd(a2 - ah[mt][2]);
                ah[mt][3] = tf32_rnd(a3); al[mt][3] = tf32_rnd(a3 - ah[mt][3]);
            }
#pragma unroll
            for (int nt = 0; nt < NT; nt++) {
                const float* bp = sB + (ks * 8 + q) * BS + warp_n * WN + nt * 8 + g;
                float b0 = bp[0];
                float b1 = bp[4 * BS];
                float bh[2], bl[2];
                bh[0] = tf32_rnd(b0); bl[0] = tf32_rnd(b0 - bh[0]);
                bh[1] = tf32_rnd(b1); bl[1] = tf32_rnd(b1 - bh[1]);
#pragma unroll
                for (int mt = 0; mt < 2; mt++) {
                    mma_tf32(acc[mt][nt], ah[mt], bh);
                    mma_tf32(acc[mt][nt], al[mt], bh);
                    mma_tf32(acc[mt][nt], ah[mt], bl);
                }
            }
        }
        __syncthreads();
    }

#pragma unroll
    for (int mt = 0; mt < 2; mt++) {
        int r0 = rowBase + warp_m * 32 + mt * 16 + g;
        int r1 = r0 + 8;
#pragma unroll
        for (int nt = 0; nt < NT; nt++) {
            int col = colBase + warp_n * WN + nt * 8 + 2 * q;
            if (r0 < M)
                *(float2*)(C + (size_t)r0 * N + col) = make_float2(acc[mt][nt][0], acc[mt][nt][1]);
            if (r1 < M)
                *(float2*)(C + (size_t)r1 * N + col) = make_float2(acc[mt][nt][2], acc[mt][nt][3]);
        }
    }
}

// ---------------- FUSED: H-tile = relu(A_hat @ XW1) gathered to smem, then @ W2 ----------------
// block = 128 rows; K = 128; N = 64; 256 threads (8 warps, 4x2).
__global__ __launch_bounds__(256)
void fused_spmm_gemm2(const float* __restrict__ XW1,
                      const float* __restrict__ W2,
                      float* __restrict__ C, int M) {
    constexpr int AS2 = 132;
    constexpr int BS2 = 72;
    extern __shared__ float smem[];
    float* sA = smem;                 // 128 x 132
    float* sB = smem + 128 * AS2;     // 128 x 72

    const int tid  = threadIdx.x;
    const int lane = tid & 31;
    const int wid  = tid >> 5;
    const int rowBase = blockIdx.x * 128;

    // load W2 (128 x 64) into smem
#pragma unroll
    for (int i = 0; i < 8; i++) {
        int e = tid + i * 256;
        int r = e >> 4;
        int c4 = (e & 15) * 4;
        *(float4*)(sB + r * BS2 + c4) = *(const float4*)(W2 + r * 64 + c4);
    }

    // gather phase: warp handles 16 contiguous rows
#pragma unroll 1
    for (int i = 0; i < 16; i++) {
        int lr = wid * 16 + i;
        int row = rowBase + lr;
        float4 acc = make_float4(0.f, 0.f, 0.f, 0.f);
        if (row < M) {
            int e   = g_rowptr[row];
            int end = g_rowptr[row + 1];
            for (; e + 3 < end; e += 4) {
                int2 e0 = g_edge[e];
                int2 e1 = g_edge[e + 1];
                int2 e2 = g_edge[e + 2];
                int2 e3 = g_edge[e + 3];
                float4 v0 = ((const float4*)(XW1 + (size_t)e0.x * 128))[lane];
                float4 v1 = ((const float4*)(XW1 + (size_t)e1.x * 128))[lane];
                float4 v2 = ((const float4*)(XW1 + (size_t)e2.x * 128))[lane];
                float4 v3 = ((const float4*)(XW1 + (size_t)e3.x * 128))[lane];
                float w0 = __int_as_float(e0.y), w1 = __int_as_float(e1.y);
                float w2 = __int_as_float(e2.y), w3 = __int_as_float(e3.y);
                acc.x += w0 * v0.x + w1 * v1.x + w2 * v2.x + w3 * v3.x;
                acc.y += w0 * v0.y + w1 * v1.y + w2 * v2.y + w3 * v3.y;
                acc.z += w0 * v0.z + w1 * v1.z + w2 * v2.z + w3 * v3.z;
                acc.w += w0 * v0.w + w1 * v1.w + w2 * v2.w + w3 * v3.w;
            }
            for (; e < end; e++) {
                int2 ed = g_edge[e];
                float w = __int_as_float(ed.y);
                float4 v = ((const float4*)(XW1 + (size_t)ed.x * 128))[lane];
                acc.x += w * v.x; acc.y += w * v.y;
                acc.z += w * v.z; acc.w += w * v.w;
            }
        }
        // ReLU + stage into mma A tile
        acc.x = fmaxf(acc.x, 0.f); acc.y = fmaxf(acc.y, 0.f);
        acc.z = fmaxf(acc.z, 0.f); acc.w = fmaxf(acc.w, 0.f);
        *(float4*)(sA + lr * AS2 + lane * 4) = acc;
    }
    __syncthreads();

    // mma phase: 128x64x128, tf32x3
    const int warp_m = wid & 3;
    const int warp_n = wid >> 2;
    const int g = lane >> 2;
    const int q = lane & 3;

    float acc[2][4][4];
#pragma unroll
    for (int mt = 0; mt < 2; mt++)
#pragma unroll
        for (int nt = 0; nt < 4; nt++)
#pragma unroll
            for (int r = 0; r < 4; r++) acc[mt][nt][r] = 0.f;

#pragma unroll
    for (int ks = 0; ks < 16; ks++) {
        float ah[2][4], al[2][4];
#pragma unroll
        for (int mt = 0; mt < 2; mt++) {
            const float* ap = sA + (warp_m * 32 + mt * 16 + g) * AS2 + ks * 8 + q;
            float a0 = ap[0];
            float a1 = ap[8 * AS2];
            float a2 = ap[4];
            float a3 = ap[8 * AS2 + 4];
            ah[mt][0] = tf32_rnd(a0); al[mt][0] = tf32_rnd(a0 - ah[mt][0]);
            ah[mt][1] = tf32_rnd(a1); al[mt][1] = tf32_rnd(a1 - ah[mt][1]);
            ah[mt][2] = tf32_rnd(a2); al[mt][2] = tf32_rnd(a2 - ah[mt][2]);
            ah[mt][3] = tf32_rnd(a3); al[mt][3] = tf32_rnd(a3 - ah[mt][3]);
        }
#pragma unroll
        for (int nt = 0; nt < 4; nt++) {
            const float* bp = sB + (ks * 8 + q) * BS2 + warp_n * 32 + nt * 8 + g;
            float b0 = bp[0];
            float b1 = bp[4 * BS2];
            float bh[2], bl[2];
            bh[0] = tf32_rnd(b0); bl[0] = tf32_rnd(b0 - bh[0]);
            bh[1] = tf32_rnd(b1); bl[1] = tf32_rnd(b1 - bh[1]);
#pragma unroll
            for (int mt = 0; mt < 2; mt++) {
                mma_tf32(acc[mt][nt], ah[mt], bh);
                mma_tf32(acc[mt][nt], al[mt], bh);
                mma_tf32(acc[mt][nt], ah[mt], bl);
            }
        }
    }

    // epilogue -> C (HW2), N = 64
#pragma unroll
    for (int mt = 0; mt < 2; mt++) {
        int r0 = rowBase + warp_m * 32 + mt * 16 + g;
        int r1 = r0 + 8;
#pragma unroll
        for (int nt = 0; nt < 4; nt++) {
            int col = warp_n * 32 + nt * 8 + 2 * q;
            if (r0 < M)
                *(float2*)(C + (size_t)r0 * 64 + col) = make_float2(acc[mt][nt][0], acc[mt][nt][1]);
            if (r1 < M)
                *(float2*)(C + (size_t)r1 * 64 + col) = make_float2(acc[mt][nt][2], acc[mt][nt][3]);
        }
    }
}

// ---------------- CSR SPMM, width 64: one warp per row ----------------
__global__ __launch_bounds__(256) void spmm_csr64(const float* __restrict__ src,
                                                  float* __restrict__ dst) {
    int row = blockIdx.x * 8 + (threadIdx.x >> 5);
    if (row >= N_NODES) return;
    int lane = threadIdx.x & 31;
    int e   = g_rowptr[row];
    int end = g_rowptr[row + 1];

    float2 acc = make_float2(0.f, 0.f);
    for (; e + 3 < end; e += 4) {
        int2 e0 = g_edge[e];
        int2 e1 = g_edge[e + 1];
        int2 e2 = g_edge[e + 2];
        int2 e3 = g_edge[e + 3];
        float2 v0 = ((const float2*)(src + (size_t)e0.x * 64))[lane];
        float2 v1 = ((const float2*)(src + (size_t)e1.x * 64))[lane];
        float2 v2 = ((const float2*)(src + (size_t)e2.x * 64))[lane];
        float2 v3 = ((const float2*)(src + (size_t)e3.x * 64))[lane];
        float w0 = __int_as_float(e0.y), w1 = __int_as_float(e1.y);
        float w2 = __int_as_float(e2.y), w3 = __int_as_float(e3.y);
        acc.x += w0 * v0.x + w1 * v1.x + w2 * v2.x + w3 * v3.x;
        acc.y += w0 * v0.y + w1 * v1.y + w2 * v2.y + w3 * v3.y;
    }
    for (; e < end; e++) {
        int2 ed = g_edge[e];
        float w = __int_as_float(ed.y);
        float2 v = ((const float2*)(src + (size_t)ed.x * 64))[lane];
        acc.x += w * v.x;
        acc.y += w * v.y;
    }
    ((float2*)(dst + (size_t)row * 64))[lane] = acc;
}

// ---------------- launch ----------------
extern "C" void kernel_launch(void* const* d_in, const int* in_sizes, int n_in,
                              void* d_out, int out_size) {
    const float* X  = (const float*)d_in[0];
    const float* W1 = (const float*)d_in[1];
    const float* W2 = (const float*)d_in[2];
    const int* er   = (const int*)d_in[3];
    const int* ec   = (const int*)d_in[4];
    float* out = (float*)d_out;

    const int M  = in_sizes[0] / 256;   // 100000
    const int nE = in_sizes[3];         // 1700000
    const int nE4 = nE / 4;

    float *p_xw1, *p_hw2;
    cudaGetSymbolAddress((void**)&p_xw1, g_XW1);
    cudaGetSymbolAddress((void**)&p_hw2, g_HW2);

    const int smem1  = 2 * (128 * 36 + 32 * (128 + 8)) * 4;   // 71680
    const int smemF  = (128 * 132 + 128 * 72) * 4;            // 104448

    static cudaStream_t s_side = nullptr;
    static cudaEvent_t  ev_fork = nullptr, ev_join = nullptr;
    if (!s_side) {
        cudaStreamCreateWithFlags(&s_side, cudaStreamNonBlocking);
        cudaEventCreateWithFlags(&ev_fork, cudaEventDisableTiming);
        cudaEventCreateWithFlags(&ev_join, cudaEventDisableTiming);
        cudaFuncSetAttribute(mma_gemm_kernel<128>,
                             cudaFuncAttributeMaxDynamicSharedMemorySize, smem1);
        cudaFuncSetAttribute(fused_spmm_gemm2,
                             cudaFuncAttributeMaxDynamicSharedMemorySize, smemF);
    }

    // ---- fork: CSR build on side stream, GEMM1 on main stream ----
    cudaEventRecord(ev_fork, 0);
    cudaStreamWaitEvent(s_side, ev_fork, 0);

    zero_deg_kernel<<<(N_NODES + 255) / 256, 256, 0, s_side>>>();
    deg_kernel<<<(nE4 + 3 + 255) / 256, 256, 0, s_side>>>(er, nE4, nE);
    dinv_kernel<<<(N_NODES + 255) / 256, 256, 0, s_side>>>();
    scanA_kernel<<<NUM_SB, SCAN_B, 0, s_side>>>();
    scanB_kernel<<<1, 128, 0, s_side>>>(NUM_SB);
    scanC_kernel<<<NUM_SB, SCAN_B, 0, s_side>>>(nE);
    scatter_kernel<<<(nE4 + 3 + 255) / 256, 256, 0, s_side>>>(er, ec, nE4, nE);
    cudaEventRecord(ev_join, s_side);

    // main stream: GEMM1 (independent of CSR)
    {
        dim3 grid(1, (M + 127) / 128);
        mma_gemm_kernel<128><<<grid, 256, smem1>>>(M, 128, 256, X, W1, p_xw1);
    }

    // ---- join ----
    cudaStreamWaitEvent(0, ev_join, 0);

    // fused: HW2 = relu(A_hat @ XW1) @ W2
    fused_spmm_gemm2<<<(M + 127) / 128, 256, smemF>>>(p_xw1, W2, p_hw2, M);

    // out = A_hat @ HW2
    spmm_csr64<<<(N_NODES + 7) / 8, 256>>>(p_hw2, out);
}

// round 5
// speedup vs baseline: 1.1673x; 1.1673x over previous
#include <cuda_runtime.h>
#include <cstdint>

#define N_NODES 100000
#define NE_MAX  1700032
#define SCAN_B  1024
#define NUM_SB  ((N_NODES + SCAN_B - 1) / SCAN_B)   // 98

// ---------------- scratch (alloc-free rule: __device__ globals) ----------------
__device__ int   g_deg   [N_NODES];
__device__ float g_dinv  [N_NODES];
__device__ int   g_rowptr[N_NODES + 1];
__device__ int   g_cursor[N_NODES];
__device__ int   g_bsum  [128];
__device__ __align__(16) int2  g_edge[NE_MAX];     // {col, w_bits} interleaved
__device__ __align__(16) float g_XW1[(size_t)N_NODES * 128];
__device__ __align__(16) float g_H  [(size_t)N_NODES * 128];
__device__ __align__(16) float g_HW2[(size_t)N_NODES * 64];

// ---------------- small helpers ----------------
__device__ __forceinline__ float tf32_rnd(float x) {
    float r;
    asm("cvt.rna.tf32.f32 %0, %1;" : "=f"(r) : "f"(x));
    return r;
}

__device__ __forceinline__ void mma_tf32(float c[4], const float a[4], const float b[2]) {
    asm volatile(
        "mma.sync.aligned.m16n8k8.row.col.f32.tf32.tf32.f32 "
        "{%0,%1,%2,%3}, {%4,%5,%6,%7}, {%8,%9}, {%0,%1,%2,%3};"
        : "+f"(c[0]), "+f"(c[1]), "+f"(c[2]), "+f"(c[3])
        : "r"(__float_as_uint(a[0])), "r"(__float_as_uint(a[1])),
          "r"(__float_as_uint(a[2])), "r"(__float_as_uint(a[3])),
          "r"(__float_as_uint(b[0])), "r"(__float_as_uint(b[1])));
}

__device__ __forceinline__ void cp_async16(void* smem_dst, const void* gsrc, bool valid) {
    uint32_t d = (uint32_t)__cvta_generic_to_shared(smem_dst);
    int sz = valid ? 16 : 0;
    asm volatile("cp.async.cg.shared.global [%0], [%1], 16, %2;"
                 :: "r"(d), "l"(gsrc), "r"(sz) : "memory");
}

// ---------------- CSR build ----------------
__global__ void zero_deg_kernel() {
    int i = blockIdx.x * blockDim.x + threadIdx.x;
    if (i < N_NODES) g_deg[i] = 0;
}

__global__ void deg_kernel(const int* __restrict__ rows, int nE4, int nE) {
    int i = blockIdx.x * blockDim.x + threadIdx.x;
    if (i < nE4) {
        int4 r = ((const int4*)rows)[i];
        atomicAdd(&g_deg[r.x], 1);
        atomicAdd(&g_deg[r.y], 1);
        atomicAdd(&g_deg[r.z], 1);
        atomicAdd(&g_deg[r.w], 1);
    } else {
        int j = nE4 * 4 + (i - nE4);
        if (j < nE) atomicAdd(&g_deg[rows[j]], 1);
    }
}

__global__ void dinv_kernel() {
    int i = blockIdx.x * blockDim.x + threadIdx.x;
    if (i < N_NODES) g_dinv[i] = rsqrtf((float)max(g_deg[i], 1));
}

__global__ __launch_bounds__(SCAN_B) void scanA_kernel() {
    __shared__ int s[SCAN_B];
    int tid = threadIdx.x;
    int i = blockIdx.x * SCAN_B + tid;
    int v = (i < N_NODES) ? g_deg[i] : 0;
    s[tid] = v;
    __syncthreads();
#pragma unroll
    for (int off = 1; off < SCAN_B; off <<= 1) {
        int t = (tid >= off) ? s[tid - off] : 0;
        __syncthreads();
        s[tid] += t;
        __syncthreads();
    }
    if (i < N_NODES) g_rowptr[i] = s[tid] - v;
    if (tid == SCAN_B - 1) g_bsum[blockIdx.x] = s[tid];
}

__global__ void scanB_kernel(int nb) {
    __shared__ int s[128];
    int tid = threadIdx.x;
    int v = (tid < nb) ? g_bsum[tid] : 0;
    s[tid] = v;
    __syncthreads();
#pragma unroll
    for (int off = 1; off < 128; off <<= 1) {
        int t = (tid >= off) ? s[tid - off] : 0;
        __syncthreads();
        s[tid] += t;
        __syncthreads();
    }
    if (tid < nb) g_bsum[tid] = s[tid] - v;
}

__global__ __launch_bounds__(SCAN_B) void scanC_kernel(int nE) {
    int i = blockIdx.x * SCAN_B + threadIdx.x;
    if (i < N_NODES) {
        int rp = g_rowptr[i] + g_bsum[blockIdx.x];
        g_rowptr[i] = rp;
        g_cursor[i] = rp;
    }
    if (i == 0) g_rowptr[N_NODES] = nE;
}

__device__ __forceinline__ void scatter_one(int r, int c) {
    int pos = atomicAdd(&g_cursor[r], 1);
    float w = g_dinv[r] * g_dinv[c];
    g_edge[pos] = make_int2(c, __float_as_int(w));
}

__global__ void scatter_kernel(const int* __restrict__ rows, const int* __restrict__ cols,
                               int nE4, int nE) {
    int i = blockIdx.x * blockDim.x + threadIdx.x;
    if (i < nE4) {
        int4 r = ((const int4*)rows)[i];
        int4 c = ((const int4*)cols)[i];
        scatter_one(r.x, c.x);
        scatter_one(r.y, c.y);
        scatter_one(r.z, c.z);
        scatter_one(r.w, c.w);
    } else {
        int j = nE4 * 4 + (i - nE4);
        if (j < nE) scatter_one(rows[j], cols[j]);
    }
}

// ---------------- TF32 tensor-core GEMM (3xTF32): C = A @ B ----------------
template <int BN>
__global__ __launch_bounds__(256)
void mma_gemm_kernel(int M, int N, int K,
                     const float* __restrict__ A,
                     const float* __restrict__ B,
                     float* __restrict__ C) {
    constexpr int BM = 128;
    constexpr int BK = 32;
    constexpr int AS = 36;
    constexpr int BS = BN + 8;
    constexpr int A_STAGE = BM * AS;
    constexpr int B_STAGE = BK * BS;
    constexpr int STAGE   = A_STAGE + B_STAGE;
    constexpr int WN = BN / 2;
    constexpr int NT = WN / 8;
    constexpr int B_LD = (BK * BN / 4) / 256;

    extern __shared__ float smem[];

    const int tid    = threadIdx.x;
    const int lane   = tid & 31;
    const int wid    = tid >> 5;
    const int warp_m = wid & 3;
    const int warp_n = wid >> 2;
    const int g      = lane >> 2;
    const int q      = lane & 3;
    const int rowBase = blockIdx.y * BM;
    const int colBase = blockIdx.x * BN;

    float acc[2][NT][4];
#pragma unroll
    for (int mt = 0; mt < 2; mt++)
#pragma unroll
        for (int nt = 0; nt < NT; nt++)
#pragma unroll
            for (int r = 0; r < 4; r++) acc[mt][nt][r] = 0.f;

    const int NITER = K / BK;

    auto load_tile = [&](int stage, int k0) {
        float* sA = smem + stage * STAGE;
        float* sB = sA + A_STAGE;
#pragma unroll
        for (int i = 0; i < 4; i++) {
            int e = tid + i * 256;
            int r = e >> 3;
            int c4 = (e & 7) * 4;
            int gr = rowBase + r;
            cp_async16(sA + r * AS + c4, A + (size_t)gr * K + k0 + c4, gr < M);
        }
#pragma unroll
        for (int i = 0; i < B_LD; i++) {
            int e = tid + i * 256;
            int r = e / (BN / 4);
            int c4 = (e % (BN / 4)) * 4;
            cp_async16(sB + r * BS + c4, B + (size_t)(k0 + r) * N + colBase + c4, true);
        }
        asm volatile("cp.async.commit_group;" ::: "memory");
    };

    load_tile(0, 0);

    for (int it = 0; it < NITER; ++it) {
        int cur = it & 1;
        if (it + 1 < NITER) {
            load_tile(cur ^ 1, (it + 1) * BK);
            asm volatile("cp.async.wait_group 1;" ::: "memory");
        } else {
            asm volatile("cp.async.wait_group 0;" ::: "memory");
        }
        __syncthreads();

        const float* sA = smem + cur * STAGE;
        const float* sB = sA + A_STAGE;

#pragma unroll
        for (int ks = 0; ks < 4; ks++) {
            float ah[2][4], al[2][4];
#pragma unroll
            for (int mt = 0; mt < 2; mt++) {
                const float* ap = sA + (warp_m * 32 + mt * 16 + g) * AS + ks * 8 + q;
                float a0 = ap[0];
                float a1 = ap[8 * AS];
                float a2 = ap[4];
                float a3 = ap[8 * AS + 4];
                ah[mt][0] = tf32_rnd(a0); al[mt][0] = tf32_rnd(a0 - ah[mt][0]);
                ah[mt][1] = tf32_rnd(a1); al[mt][1] = tf32_rnd(a1 - ah[mt][1]);
                ah[mt][2] = tf32_rnd(a2); al[mt][2] = tf32_rnd(a2 - ah[mt][2]);
                ah[mt][3] = tf32_rnd(a3); al[mt][3] = tf32_rnd(a3 - ah[mt][3]);
            }
#pragma unroll
            for (int nt = 0; nt < NT; nt++) {
                const float* bp = sB + (ks * 8 + q) * BS + warp_n * WN + nt * 8 + g;
                float b0 = bp[0];
                float b1 = bp[4 * BS];
                float bh[2], bl[2];
                bh[0] = tf32_rnd(b0); bl[0] = tf32_rnd(b0 - bh[0]);
                bh[1] = tf32_rnd(b1); bl[1] = tf32_rnd(b1 - bh[1]);
#pragma unroll
                for (int mt = 0; mt < 2; mt++) {
                    mma_tf32(acc[mt][nt], ah[mt], bh);
                    mma_tf32(acc[mt][nt], al[mt], bh);
                    mma_tf32(acc[mt][nt], ah[mt], bl);
                }
            }
        }
        __syncthreads();
    }

#pragma unroll
    for (int mt = 0; mt < 2; mt++) {
        int r0 = rowBase + warp_m * 32 + mt * 16 + g;
        int r1 = r0 + 8;
#pragma unroll
        for (int nt = 0; nt < NT; nt++) {
            int col = colBase + warp_n * WN + nt * 8 + 2 * q;
            if (r0 < M)
                *(float2*)(C + (size_t)r0 * N + col) = make_float2(acc[mt][nt][0], acc[mt][nt][1]);
            if (r1 < M)
                *(float2*)(C + (size_t)r1 * N + col) = make_float2(acc[mt][nt][2], acc[mt][nt][3]);
        }
    }
}

// ---------------- CSR SPMM, width 128: one warp per row (+ReLU on store) ----------------
__global__ __launch_bounds__(256) void spmm_csr128(const float* __restrict__ src,
                                                   float* __restrict__ dst) {
    int row = blockIdx.x * 8 + (threadIdx.x >> 5);
    if (row >= N_NODES) return;
    int lane = threadIdx.x & 31;
    int e   = g_rowptr[row];
    int end = g_rowptr[row + 1];

    float4 acc = make_float4(0.f, 0.f, 0.f, 0.f);
    for (; e + 3 < end; e += 4) {
        int2 e0 = g_edge[e];
        int2 e1 = g_edge[e + 1];
        int2 e2 = g_edge[e + 2];
        int2 e3 = g_edge[e + 3];
        float4 v0 = ((const float4*)(src + (size_t)e0.x * 128))[lane];
        float4 v1 = ((const float4*)(src + (size_t)e1.x * 128))[lane];
        float4 v2 = ((const float4*)(src + (size_t)e2.x * 128))[lane];
        float4 v3 = ((const float4*)(src + (size_t)e3.x * 128))[lane];
        float w0 = __int_as_float(e0.y), w1 = __int_as_float(e1.y);
        float w2 = __int_as_float(e2.y), w3 = __int_as_float(e3.y);
        acc.x += w0 * v0.x + w1 * v1.x + w2 * v2.x + w3 * v3.x;
        acc.y += w0 * v0.y + w1 * v1.y + w2 * v2.y + w3 * v3.y;
        acc.z += w0 * v0.z + w1 * v1.z + w2 * v2.z + w3 * v3.z;
        acc.w += w0 * v0.w + w1 * v1.w + w2 * v2.w + w3 * v3.w;
    }
    for (; e < end; e++) {
        int2 ed = g_edge[e];
        float w = __int_as_float(ed.y);
        float4 v = ((const float4*)(src + (size_t)ed.x * 128))[lane];
        acc.x += w * v.x; acc.y += w * v.y;
        acc.z += w * v.z; acc.w += w * v.w;
    }
    // fused ReLU (H is only consumed as relu(H))
    acc.x = fmaxf(acc.x, 0.f); acc.y = fmaxf(acc.y, 0.f);
    acc.z = fmaxf(acc.z, 0.f); acc.w = fmaxf(acc.w, 0.f);
    ((float4*)(dst + (size_t)row * 128))[lane] = acc;
}

// ---------------- CSR SPMM, width 64: one warp per row ----------------
__global__ __launch_bounds__(256) void spmm_csr64(const float* __restrict__ src,
                                                  float* __restrict__ dst) {
    int row = blockIdx.x * 8 + (threadIdx.x >> 5);
    if (row >= N_NODES) return;
    int lane = threadIdx.x & 31;
    int e   = g_rowptr[row];
    int end = g_rowptr[row + 1];

    float2 acc = make_float2(0.f, 0.f);
    for (; e + 3 < end; e += 4) {
        int2 e0 = g_edge[e];
        int2 e1 = g_edge[e + 1];
        int2 e2 = g_edge[e + 2];
        int2 e3 = g_edge[e + 3];
        float2 v0 = ((const float2*)(src + (size_t)e0.x * 64))[lane];
        float2 v1 = ((const float2*)(src + (size_t)e1.x * 64))[lane];
        float2 v2 = ((const float2*)(src + (size_t)e2.x * 64))[lane];
        float2 v3 = ((const float2*)(src + (size_t)e3.x * 64))[lane];
        float w0 = __int_as_float(e0.y), w1 = __int_as_float(e1.y);
        float w2 = __int_as_float(e2.y), w3 = __int_as_float(e3.y);
        acc.x += w0 * v0.x + w1 * v1.x + w2 * v2.x + w3 * v3.x;
        acc.y += w0 * v0.y + w1 * v1.y + w2 * v2.y + w3 * v3.y;
    }
    for (; e < end; e++) {
        int2 ed = g_edge[e];
        float w = __int_as_float(ed.y);
        float2 v = ((const float2*)(src + (size_t)ed.x * 64))[lane];
        acc.x += w * v.x;
        acc.y += w * v.y;
    }
    ((float2*)(dst + (size_t)row * 64))[lane] = acc;
}

// ---------------- launch ----------------
extern "C" void kernel_launch(void* const* d_in, const int* in_sizes, int n_in,
                              void* d_out, int out_size) {
    const float* X  = (const float*)d_in[0];
    const float* W1 = (const float*)d_in[1];
    const float* W2 = (const float*)d_in[2];
    const int* er   = (const int*)d_in[3];
    const int* ec   = (const int*)d_in[4];
    float* out = (float*)d_out;

    const int M  = in_sizes[0] / 256;   // 100000
    const int nE = in_sizes[3];         // 1700000
    const int nE4 = nE / 4;

    float *p_xw1, *p_h, *p_hw2;
    cudaGetSymbolAddress((void**)&p_xw1, g_XW1);
    cudaGetSymbolAddress((void**)&p_h,   g_H);
    cudaGetSymbolAddress((void**)&p_hw2, g_HW2);

    const int smem1 = 2 * (128 * 36 + 32 * (128 + 8)) * 4;   // 71680
    const int smem2 = 2 * (128 * 36 + 32 * (64 + 8)) * 4;    // 55296

    static cudaStream_t s_side = nullptr;
    static cudaEvent_t  ev_fork = nullptr, ev_join = nullptr;
    if (!s_side) {
        cudaStreamCreateWithFlags(&s_side, cudaStreamNonBlocking);
        cudaEventCreateWithFlags(&ev_fork, cudaEventDisableTiming);
        cudaEventCreateWithFlags(&ev_join, cudaEventDisableTiming);
        cudaFuncSetAttribute(mma_gemm_kernel<128>,
                             cudaFuncAttributeMaxDynamicSharedMemorySize, smem1);
        cudaFuncSetAttribute(mma_gemm_kernel<64>,
                             cudaFuncAttributeMaxDynamicSharedMemorySize, smem2);
    }

    // ---- fork: CSR build on side stream, GEMM1 on main stream ----
    cudaEventRecord(ev_fork, 0);
    cudaStreamWaitEvent(s_side, ev_fork, 0);

    zero_deg_kernel<<<(N_NODES + 255) / 256, 256, 0, s_side>>>();
    deg_kernel<<<(nE4 + 3 + 255) / 256, 256, 0, s_side>>>(er, nE4, nE);
    dinv_kernel<<<(N_NODES + 255) / 256, 256, 0, s_side>>>();
    scanA_kernel<<<NUM_SB, SCAN_B, 0, s_side>>>();
    scanB_kernel<<<1, 128, 0, s_side>>>(NUM_SB);
    scanC_kernel<<<NUM_SB, SCAN_B, 0, s_side>>>(nE);
    scatter_kernel<<<(nE4 + 3 + 255) / 256, 256, 0, s_side>>>(er, ec, nE4, nE);
    cudaEventRecord(ev_join, s_side);

    // main stream: GEMM1 (independent of CSR)
    {
        dim3 grid(1, (M + 127) / 128);
        mma_gemm_kernel<128><<<grid, 256, smem1>>>(M, 128, 256, X, W1, p_xw1);
    }

    // ---- join ----
    cudaStreamWaitEvent(0, ev_join, 0);

    // ---- SPMM1: H = relu(A_hat @ XW1) (width 128) ----
    spmm_csr128<<<(N_NODES + 7) / 8, 256>>>(p_xw1, p_h);

    // ---- GEMM2: HW2 = H @ W2  (M x 128 x 64), tf32x3 tensor-core ----
    {
        dim3 grid(1, (M + 127) / 128);
        mma_gemm_kernel<64><<<grid, 256, smem2>>>(M, 64, 128, p_h, W2, p_hw2);
    }

    // ---- SPMM2: out = A_hat @ HW2 (width 64) ----
    spmm_csr64<<<(N_NODES + 7) / 8, 256>>>(p_hw2, out);
}

// round 6
// speedup vs baseline: 1.3975x; 1.1972x over previous
#include <cuda_runtime.h>
#include <cuda_fp16.h>
#include <cstdint>

#define N_NODES 100000
#define NE_MAX  1700032
#define SCAN_B  1024
#define NUM_SB  ((N_NODES + SCAN_B - 1) / SCAN_B)   // 98

// ---------------- scratch (alloc-free rule: __device__ globals) ----------------
__device__ int   g_deg   [N_NODES];
__device__ float g_dinv  [N_NODES];
__device__ int   g_rowptr[N_NODES + 1];
__device__ int   g_cursor[N_NODES];
__device__ int   g_bsum  [128];
__device__ __align__(16) int2   g_edge[NE_MAX];     // {col, w_bits}
__device__ __align__(16) __half g_XW1h[(size_t)N_NODES * 128];
__device__ __align__(16) __half g_Hh  [(size_t)N_NODES * 128];
__device__ __align__(16) __half g_HW2h[(size_t)N_NODES * 64];

// ---------------- small helpers ----------------
__device__ __forceinline__ float tf32_rnd(float x) {
    float r;
    asm("cvt.rna.tf32.f32 %0, %1;" : "=f"(r) : "f"(x));
    return r;
}

__device__ __forceinline__ void mma_tf32(float c[4], const float a[4], const float b[2]) {
    asm volatile(
        "mma.sync.aligned.m16n8k8.row.col.f32.tf32.tf32.f32 "
        "{%0,%1,%2,%3}, {%4,%5,%6,%7}, {%8,%9}, {%0,%1,%2,%3};"
        : "+f"(c[0]), "+f"(c[1]), "+f"(c[2]), "+f"(c[3])
        : "r"(__float_as_uint(a[0])), "r"(__float_as_uint(a[1])),
          "r"(__float_as_uint(a[2])), "r"(__float_as_uint(a[3])),
          "r"(__float_as_uint(b[0])), "r"(__float_as_uint(b[1])));
}

__device__ __forceinline__ void cp_async16(void* smem_dst, const void* gsrc, bool valid) {
    uint32_t d = (uint32_t)__cvta_generic_to_shared(smem_dst);
    int sz = valid ? 16 : 0;
    asm volatile("cp.async.cg.shared.global [%0], [%1], 16, %2;"
                 :: "r"(d), "l"(gsrc), "r"(sz) : "memory");
}

// ---------------- CSR build ----------------
__global__ void zero_deg_kernel() {
    int i = blockIdx.x * blockDim.x + threadIdx.x;
    if (i < N_NODES) g_deg[i] = 0;
}

__global__ void deg_kernel(const int* __restrict__ rows, int nE4, int nE) {
    int i = blockIdx.x * blockDim.x + threadIdx.x;
    if (i < nE4) {
        int4 r = ((const int4*)rows)[i];
        atomicAdd(&g_deg[r.x], 1);
        atomicAdd(&g_deg[r.y], 1);
        atomicAdd(&g_deg[r.z], 1);
        atomicAdd(&g_deg[r.w], 1);
    } else {
        int j = nE4 * 4 + (i - nE4);
        if (j < nE) atomicAdd(&g_deg[rows[j]], 1);
    }
}

__global__ void dinv_kernel() {
    int i = blockIdx.x * blockDim.x + threadIdx.x;
    if (i < N_NODES) g_dinv[i] = rsqrtf((float)max(g_deg[i], 1));
}

__global__ __launch_bounds__(SCAN_B) void scanA_kernel() {
    __shared__ int s[SCAN_B];
    int tid = threadIdx.x;
    int i = blockIdx.x * SCAN_B + tid;
    int v = (i < N_NODES) ? g_deg[i] : 0;
    s[tid] = v;
    __syncthreads();
#pragma unroll
    for (int off = 1; off < SCAN_B; off <<= 1) {
        int t = (tid >= off) ? s[tid - off] : 0;
        __syncthreads();
        s[tid] += t;
        __syncthreads();
    }
    if (i < N_NODES) g_rowptr[i] = s[tid] - v;
    if (tid == SCAN_B - 1) g_bsum[blockIdx.x] = s[tid];
}

__global__ void scanB_kernel(int nb) {
    __shared__ int s[128];
    int tid = threadIdx.x;
    int v = (tid < nb) ? g_bsum[tid] : 0;
    s[tid] = v;
    __syncthreads();
#pragma unroll
    for (int off = 1; off < 128; off <<= 1) {
        int t = (tid >= off) ? s[tid - off] : 0;
        __syncthreads();
        s[tid] += t;
        __syncthreads();
    }
    if (tid < nb) g_bsum[tid] = s[tid] - v;
}

__global__ __launch_bounds__(SCAN_B) void scanC_kernel(int nE) {
    int i = blockIdx.x * SCAN_B + threadIdx.x;
    if (i < N_NODES) {
        int rp = g_rowptr[i] + g_bsum[blockIdx.x];
        g_rowptr[i] = rp;
        g_cursor[i] = rp;
    }
    if (i == 0) g_rowptr[N_NODES] = nE;
}

__device__ __forceinline__ void scatter_one(int r, int c) {
    int pos = atomicAdd(&g_cursor[r], 1);
    float w = g_dinv[r] * g_dinv[c];
    g_edge[pos] = make_int2(c, __float_as_int(w));
}

__global__ void scatter_kernel(const int* __restrict__ rows, const int* __restrict__ cols,
                               int nE4, int nE) {
    int i = blockIdx.x * blockDim.x + threadIdx.x;
    if (i < nE4) {
        int4 r = ((const int4*)rows)[i];
        int4 c = ((const int4*)cols)[i];
        scatter_one(r.x, c.x);
        scatter_one(r.y, c.y);
        scatter_one(r.z, c.z);
        scatter_one(r.w, c.w);
    } else {
        int j = nE4 * 4 + (i - nE4);
        if (j < nE) scatter_one(rows[j], cols[j]);
    }
}

// ---------------- GEMM1: XW1h = X @ W1 (fp32 in, tf32x3, fp16 out) ----------------
// M x 128 x 256; 256 threads (8 warps 4x2); BM=128, BN=128, BK=32.
__global__ __launch_bounds__(256)
void mma_gemm1(int M, const float* __restrict__ A,
               const float* __restrict__ B, __half* __restrict__ C) {
    constexpr int BN = 128, BK = 32, K = 256, N = 128;
    constexpr int AS = 36;
    constexpr int BS = BN + 8;
    constexpr int A_STAGE = 128 * AS;
    constexpr int B_STAGE = BK * BS;
    constexpr int STAGE   = A_STAGE + B_STAGE;

    extern __shared__ float smem[];

    const int tid    = threadIdx.x;
    const int lane   = tid & 31;
    const int wid    = tid >> 5;
    const int warp_m = wid & 3;
    const int warp_n = wid >> 2;
    const int g      = lane >> 2;
    const int q      = lane & 3;
    const int rowBase = blockIdx.y * 128;

    float acc[2][8][4];
#pragma unroll
    for (int mt = 0; mt < 2; mt++)
#pragma unroll
        for (int nt = 0; nt < 8; nt++)
#pragma unroll
            for (int r = 0; r < 4; r++) acc[mt][nt][r] = 0.f;

    auto load_tile = [&](int stage, int k0) {
        float* sA = smem + stage * STAGE;
        float* sB = sA + A_STAGE;
#pragma unroll
        for (int i = 0; i < 4; i++) {
            int e = tid + i * 256;
            int r = e >> 3;
            int c4 = (e & 7) * 4;
            int gr = rowBase + r;
            cp_async16(sA + r * AS + c4, A + (size_t)gr * K + k0 + c4, gr < M);
        }
#pragma unroll
        for (int i = 0; i < 4; i++) {
            int e = tid + i * 256;
            int r = e >> 5;
            int c4 = (e & 31) * 4;
            cp_async16(sB + r * BS + c4, B + (size_t)(k0 + r) * N + c4, true);
        }
        asm volatile("cp.async.commit_group;" ::: "memory");
    };

    load_tile(0, 0);

    for (int it = 0; it < K / BK; ++it) {
        int cur = it & 1;
        if (it + 1 < K / BK) {
            load_tile(cur ^ 1, (it + 1) * BK);
            asm volatile("cp.async.wait_group 1;" ::: "memory");
        } else {
            asm volatile("cp.async.wait_group 0;" ::: "memory");
        }
        __syncthreads();

        const float* sA = smem + cur * STAGE;
        const float* sB = sA + A_STAGE;

#pragma unroll
        for (int ks = 0; ks < 4; ks++) {
            float ah[2][4], al[2][4];
#pragma unroll
            for (int mt = 0; mt < 2; mt++) {
                const float* ap = sA + (warp_m * 32 + mt * 16 + g) * AS + ks * 8 + q;
                float a0 = ap[0];
                float a1 = ap[8 * AS];
                float a2 = ap[4];
                float a3 = ap[8 * AS + 4];
                ah[mt][0] = tf32_rnd(a0); al[mt][0] = tf32_rnd(a0 - ah[mt][0]);
                ah[mt][1] = tf32_rnd(a1); al[mt][1] = tf32_rnd(a1 - ah[mt][1]);
                ah[mt][2] = tf32_rnd(a2); al[mt][2] = tf32_rnd(a2 - ah[mt][2]);
                ah[mt][3] = tf32_rnd(a3); al[mt][3] = tf32_rnd(a3 - ah[mt][3]);
            }
#pragma unroll
            for (int nt = 0; nt < 8; nt++) {
                const float* bp = sB + (ks * 8 + q) * BS + warp_n * 64 + nt * 8 + g;
                float b0 = bp[0];
                float b1 = bp[4 * BS];
                float bh[2], bl[2];
                bh[0] = tf32_rnd(b0); bl[0] = tf32_rnd(b0 - bh[0]);
                bh[1] = tf32_rnd(b1); bl[1] = tf32_rnd(b1 - bh[1]);
#pragma unroll
                for (int mt = 0; mt < 2; mt++) {
                    mma_tf32(acc[mt][nt], ah[mt], bh);
                    mma_tf32(acc[mt][nt], al[mt], bh);
                    mma_tf32(acc[mt][nt], ah[mt], bl);
                }
            }
        }
        __syncthreads();
    }

#pragma unroll
    for (int mt = 0; mt < 2; mt++) {
        int r0 = rowBase + warp_m * 32 + mt * 16 + g;
        int r1 = r0 + 8;
#pragma unroll
        for (int nt = 0; nt < 8; nt++) {
            int col = warp_n * 64 + nt * 8 + 2 * q;
            if (r0 < M)
                *(__half2*)(C + (size_t)r0 * N + col) = __floats2half2_rn(acc[mt][nt][0], acc[mt][nt][1]);
            if (r1 < M)
                *(__half2*)(C + (size_t)r1 * N + col) = __floats2half2_rn(acc[mt][nt][2], acc[mt][nt][3]);
        }
    }
}

// ---------------- GEMM2: HW2h = Hh @ W2 (fp16 A exact-in-tf32, 2 mma) ----------------
// M x 64 x 128; 256 threads (8 warps 4x2).
__global__ __launch_bounds__(256)
void mma_gemm2h(int M, const __half* __restrict__ A,
                const float* __restrict__ B, __half* __restrict__ C) {
    constexpr int BK = 32, AS = 36, BS = 72;
    __shared__ float sA[128 * AS];
    __shared__ float sB[BK * BS];

    const int tid    = threadIdx.x;
    const int lane   = tid & 31;
    const int wid    = tid >> 5;
    const int warp_m = wid & 3;
    const int warp_n = wid >> 2;
    const int g      = lane >> 2;
    const int q      = lane & 3;
    const int rowBase = blockIdx.x * 128;

    float acc[2][4][4];
#pragma unroll
    for (int mt = 0; mt < 2; mt++)
#pragma unroll
        for (int nt = 0; nt < 4; nt++)
#pragma unroll
            for (int r = 0; r < 4; r++) acc[mt][nt][r] = 0.f;

    for (int k0 = 0; k0 < 128; k0 += BK) {
        // A: 128 rows x 32 halves (64B/row = 4 x 16B chunks); 512 chunks, 2/thread
#pragma unroll
        for (int i = 0; i < 2; i++) {
            int e = tid + i * 256;
            int r = e >> 2;
            int c8 = (e & 3) * 8;
            int gr = rowBase + r;
            if (gr < M) {
                uint4 raw = *(const uint4*)(A + (size_t)gr * 128 + k0 + c8);
                const __half2* h = (const __half2*)&raw;
#pragma unroll
                for (int j = 0; j < 4; j++) {
                    float2 f = __half22float2(h[j]);
                    sA[r * AS + c8 + 2 * j]     = f.x;
                    sA[r * AS + c8 + 2 * j + 1] = f.y;
                }
            } else {
#pragma unroll
                for (int j = 0; j < 8; j++) sA[r * AS + c8 + j] = 0.f;
            }
        }
        // B: 32 x 64 fp32 = 512 float4... (32*64/4 = 512) -> 2/thread
#pragma unroll
        for (int i = 0; i < 2; i++) {
            int e = tid + i * 256;
            int r = e >> 4;
            int c4 = (e & 15) * 4;
            *(float4*)(sB + r * BS + c4) = *(const float4*)(B + (size_t)(k0 + r) * 64 + c4);
        }
        __syncthreads();

#pragma unroll
        for (int ks = 0; ks < 4; ks++) {
            float ah[2][4];
#pragma unroll
            for (int mt = 0; mt < 2; mt++) {
                const float* ap = sA + (warp_m * 32 + mt * 16 + g) * AS + ks * 8 + q;
                // fp16-derived values: exact in tf32, no lo term needed
                ah[mt][0] = ap[0];
                ah[mt][1] = ap[8 * AS];
                ah[mt][2] = ap[4];
                ah[mt][3] = ap[8 * AS + 4];
            }
#pragma unroll
            for (int nt = 0; nt < 4; nt++) {
                const float* bp = sB + (ks * 8 + q) * BS + warp_n * 32 + nt * 8 + g;
                float b0 = bp[0];
                float b1 = bp[4 * BS];
                float bh[2], bl[2];
                bh[0] = tf32_rnd(b0); bl[0] = tf32_rnd(b0 - bh[0]);
                bh[1] = tf32_rnd(b1); bl[1] = tf32_rnd(b1 - bh[1]);
#pragma unroll
                for (int mt = 0; mt < 2; mt++) {
                    mma_tf32(acc[mt][nt], ah[mt], bh);
                    mma_tf32(acc[mt][nt], ah[mt], bl);
                }
            }
        }
        __syncthreads();
    }

#pragma unroll
    for (int mt = 0; mt < 2; mt++) {
        int r0 = rowBase + warp_m * 32 + mt * 16 + g;
        int r1 = r0 + 8;
#pragma unroll
        for (int nt = 0; nt < 4; nt++) {
            int col = warp_n * 32 + nt * 8 + 2 * q;
            if (r0 < M)
                *(__half2*)(C + (size_t)r0 * 64 + col) = __floats2half2_rn(acc[mt][nt][0], acc[mt][nt][1]);
            if (r1 < M)
                *(__half2*)(C + (size_t)r1 * 64 + col) = __floats2half2_rn(acc[mt][nt][2], acc[mt][nt][3]);
        }
    }
}

// ---------------- SPMM1 (fp16): Hh = relu(A_hat @ XW1h), width 128 ----------------
__global__ __launch_bounds__(256) void spmm_csr128h(const __half* __restrict__ src,
                                                    __half* __restrict__ dst) {
    int row = blockIdx.x * 8 + (threadIdx.x >> 5);
    if (row >= N_NODES) return;
    int lane = threadIdx.x & 31;
    int e   = g_rowptr[row];
    int end = g_rowptr[row + 1];

    float4 acc = make_float4(0.f, 0.f, 0.f, 0.f);
    for (; e + 3 < end; e += 4) {
        int2 e0 = g_edge[e];
        int2 e1 = g_edge[e + 1];
        int2 e2 = g_edge[e + 2];
        int2 e3 = g_edge[e + 3];
        uint2 r0 = ((const uint2*)(src + (size_t)e0.x * 128))[lane];
        uint2 r1 = ((const uint2*)(src + (size_t)e1.x * 128))[lane];
        uint2 r2 = ((const uint2*)(src + (size_t)e2.x * 128))[lane];
        uint2 r3 = ((const uint2*)(src + (size_t)e3.x * 128))[lane];
        float w0 = __int_as_float(e0.y), w1 = __int_as_float(e1.y);
        float w2 = __int_as_float(e2.y), w3 = __int_as_float(e3.y);
        float2 a0 = __half22float2(*(__half2*)&r0.x), b0 = __half22float2(*(__half2*)&r0.y);
        float2 a1 = __half22float2(*(__half2*)&r1.x), b1 = __half22float2(*(__half2*)&r1.y);
        float2 a2 = __half22float2(*(__half2*)&r2.x), b2 = __half22float2(*(__half2*)&r2.y);
        float2 a3 = __half22float2(*(__half2*)&r3.x), b3 = __half22float2(*(__half2*)&r3.y);
        acc.x += w0 * a0.x + w1 * a1.x + w2 * a2.x + w3 * a3.x;
        acc.y += w0 * a0.y + w1 * a1.y + w2 * a2.y + w3 * a3.y;
        acc.z += w0 * b0.x + w1 * b1.x + w2 * b2.x + w3 * b3.x;
        acc.w += w0 * b0.y + w1 * b1.y + w2 * b2.y + w3 * b3.y;
    }
    for (; e < end; e++) {
        int2 ed = g_edge[e];
        float w = __int_as_float(ed.y);
        uint2 r0 = ((const uint2*)(src + (size_t)ed.x * 128))[lane];
        float2 a0 = __half22float2(*(__half2*)&r0.x), b0 = __half22float2(*(__half2*)&r0.y);
        acc.x += w * a0.x; acc.y += w * a0.y;
        acc.z += w * b0.x; acc.w += w * b0.y;
    }
    // fused ReLU + convert to fp16
    uint2 outv;
    *(__half2*)&outv.x = __floats2half2_rn(fmaxf(acc.x, 0.f), fmaxf(acc.y, 0.f));
    *(__half2*)&outv.y = __floats2half2_rn(fmaxf(acc.z, 0.f), fmaxf(acc.w, 0.f));
    ((uint2*)(dst + (size_t)row * 128))[lane] = outv;
}

// ---------------- SPMM2 (fp16 in, fp32 out): out = A_hat @ HW2h, width 64 ----------------
__global__ __launch_bounds__(256) void spmm_csr64h(const __half* __restrict__ src,
                                                   float* __restrict__ dst) {
    int row = blockIdx.x * 8 + (threadIdx.x >> 5);
    if (row >= N_NODES) return;
    int lane = threadIdx.x & 31;
    int e   = g_rowptr[row];
    int end = g_rowptr[row + 1];

    float2 acc = make_float2(0.f, 0.f);
    for (; e + 3 < end; e += 4) {
        int2 e0 = g_edge[e];
        int2 e1 = g_edge[e + 1];
        int2 e2 = g_edge[e + 2];
        int2 e3 = g_edge[e + 3];
        __half2 h0 = ((const __half2*)(src + (size_t)e0.x * 64))[lane];
        __half2 h1 = ((const __half2*)(src + (size_t)e1.x * 64))[lane];
        __half2 h2 = ((const __half2*)(src + (size_t)e2.x * 64))[lane];
        __half2 h3 = ((const __half2*)(src + (size_t)e3.x * 64))[lane];
        float w0 = __int_as_float(e0.y), w1 = __int_as_float(e1.y);
        float w2 = __int_as_float(e2.y), w3 = __int_as_float(e3.y);
        float2 f0 = __half22float2(h0);
        float2 f1 = __half22float2(h1);
        float2 f2 = __half22float2(h2);
        float2 f3 = __half22float2(h3);
        acc.x += w0 * f0.x + w1 * f1.x + w2 * f2.x + w3 * f3.x;
        acc.y += w0 * f0.y + w1 * f1.y + w2 * f2.y + w3 * f3.y;
    }
    for (; e < end; e++) {
        int2 ed = g_edge[e];
        float w = __int_as_float(ed.y);
        float2 f = __half22float2(((const __half2*)(src + (size_t)ed.x * 64))[lane]);
        acc.x += w * f.x;
        acc.y += w * f.y;
    }
    ((float2*)(dst + (size_t)row * 64))[lane] = acc;
}

// ---------------- launch ----------------
extern "C" void kernel_launch(void* const* d_in, const int* in_sizes, int n_in,
                              void* d_out, int out_size) {
    const float* X  = (const float*)d_in[0];
    const float* W1 = (const float*)d_in[1];
    const float* W2 = (const float*)d_in[2];
    const int* er   = (const int*)d_in[3];
    const int* ec   = (const int*)d_in[4];
    float* out = (float*)d_out;

    const int M  = in_sizes[0] / 256;   // 100000
    const int nE = in_sizes[3];         // 1700000
    const int nE4 = nE / 4;

    __half *p_xw1, *p_h, *p_hw2;
    cudaGetSymbolAddress((void**)&p_xw1, g_XW1h);
    cudaGetSymbolAddress((void**)&p_h,   g_Hh);
    cudaGetSymbolAddress((void**)&p_hw2, g_HW2h);

    const int smem1 = 2 * (128 * 36 + 32 * (128 + 8)) * 4;   // 71680

    static cudaStream_t s_side = nullptr;
    static cudaEvent_t  ev_fork = nullptr, ev_join = nullptr;
    if (!s_side) {
        cudaStreamCreateWithFlags(&s_side, cudaStreamNonBlocking);
        cudaEventCreateWithFlags(&ev_fork, cudaEventDisableTiming);
        cudaEventCreateWithFlags(&ev_join, cudaEventDisableTiming);
        cudaFuncSetAttribute(mma_gemm1,
                             cudaFuncAttributeMaxDynamicSharedMemorySize, smem1);
    }

    // ---- fork: CSR build on side stream, GEMM1 on main stream ----
    cudaEventRecord(ev_fork, 0);
    cudaStreamWaitEvent(s_side, ev_fork, 0);

    zero_deg_kernel<<<(N_NODES + 255) / 256, 256, 0, s_side>>>();
    deg_kernel<<<(nE4 + 3 + 255) / 256, 256, 0, s_side>>>(er, nE4, nE);
    dinv_kernel<<<(N_NODES + 255) / 256, 256, 0, s_side>>>();
    scanA_kernel<<<NUM_SB, SCAN_B, 0, s_side>>>();
    scanB_kernel<<<1, 128, 0, s_side>>>(NUM_SB);
    scanC_kernel<<<NUM_SB, SCAN_B, 0, s_side>>>(nE);
    scatter_kernel<<<(nE4 + 3 + 255) / 256, 256, 0, s_side>>>(er, ec, nE4, nE);
    cudaEventRecord(ev_join, s_side);

    // main stream: GEMM1 (independent of CSR)
    {
        dim3 grid(1, (M + 127) / 128);
        mma_gemm1<<<grid, 256, smem1>>>(M, X, W1, p_xw1);
    }

    // ---- join ----
    cudaStreamWaitEvent(0, ev_join, 0);

    // SPMM1: Hh = relu(A_hat @ XW1h)
    spmm_csr128h<<<(N_NODES + 7) / 8, 256>>>(p_xw1, p_h);

    // GEMM2: HW2h = Hh @ W2
    mma_gemm2h<<<(M + 127) / 128, 256>>>(M, p_h, W2, p_hw2);

    // SPMM2: out = A_hat @ HW2h
    spmm_csr64h<<<(N_NODES + 7) / 8, 256>>>(p_hw2, out);
}

// round 8
// speedup vs baseline: 1.4907x; 1.0667x over previous
#include <cuda_runtime.h>
#include <cuda_fp16.h>
#include <cstdint>

#define N_NODES 100000
#define NE_MAX  1700032
#define SCAN_B  1024
#define NUM_SB  ((N_NODES + SCAN_B - 1) / SCAN_B)   // 98

// ---------------- scratch (alloc-free rule: __device__ globals) ----------------
__device__ int   g_deg   [N_NODES];
__device__ float g_dinv  [N_NODES];
__device__ int   g_rowptr[N_NODES + 1];
__device__ int   g_cursor[N_NODES];
__device__ int   g_bsum  [128];
__device__ __align__(16) int2   g_edge[NE_MAX];     // {col, w_bits}
__device__ __align__(16) __half g_XW1h[(size_t)N_NODES * 128];
__device__ __align__(16) __half g_Hh  [(size_t)N_NODES * 128];
__device__ __align__(16) __half g_HW2h[(size_t)N_NODES * 64];
__device__ __align__(16) __half g_W2T [2][64 * 128];  // [hi/lo][n][k] transposed W2

// ---------------- small helpers ----------------
__device__ __forceinline__ float tf32_rnd(float x) {
    float r;
    asm("cvt.rna.tf32.f32 %0, %1;" : "=f"(r) : "f"(x));
    return r;
}

__device__ __forceinline__ void mma_tf32(float c[4], const float a[4], const float b[2]) {
    asm volatile(
        "mma.sync.aligned.m16n8k8.row.col.f32.tf32.tf32.f32 "
        "{%0,%1,%2,%3}, {%4,%5,%6,%7}, {%8,%9}, {%0,%1,%2,%3};"
        : "+f"(c[0]), "+f"(c[1]), "+f"(c[2]), "+f"(c[3])
        : "r"(__float_as_uint(a[0])), "r"(__float_as_uint(a[1])),
          "r"(__float_as_uint(a[2])), "r"(__float_as_uint(a[3])),
          "r"(__float_as_uint(b[0])), "r"(__float_as_uint(b[1])));
}

__device__ __forceinline__ void mma_f16(float c[4], const uint32_t a[4],
                                        uint32_t b0, uint32_t b1) {
    asm volatile(
        "mma.sync.aligned.m16n8k16.row.col.f32.f16.f16.f32 "
        "{%0,%1,%2,%3}, {%4,%5,%6,%7}, {%8,%9}, {%0,%1,%2,%3};"
        : "+f"(c[0]), "+f"(c[1]), "+f"(c[2]), "+f"(c[3])
        : "r"(a[0]), "r"(a[1]), "r"(a[2]), "r"(a[3]), "r"(b0), "r"(b1));
}

__device__ __forceinline__ void cp_async16(void* smem_dst, const void* gsrc, bool valid) {
    uint32_t d = (uint32_t)__cvta_generic_to_shared(smem_dst);
    int sz = valid ? 16 : 0;
    asm volatile("cp.async.cg.shared.global [%0], [%1], 16, %2;"
                 :: "r"(d), "l"(gsrc), "r"(sz) : "memory");
}

// ---------------- CSR build ----------------
__global__ void zero_deg_kernel() {
    int i = blockIdx.x * blockDim.x + threadIdx.x;
    if (i < N_NODES) g_deg[i] = 0;
}

// MLP-4: each thread batches 4 int4 loads (16 edges), then 16 atomics.
__global__ __launch_bounds__(256) void deg_kernel(const int* __restrict__ rows,
                                                  int nE4, int nE) {
    int t = blockIdx.x * blockDim.x + threadIdx.x;
    int nthr = gridDim.x * blockDim.x;
    int i0 = t, i1 = t + nthr, i2 = t + 2 * nthr, i3 = t + 3 * nthr;
    int4 v0, v1, v2, v3;
    bool p0 = i0 < nE4, p1 = i1 < nE4, p2 = i2 < nE4, p3 = i3 < nE4;
    if (p0) v0 = ((const int4*)rows)[i0];
    if (p1) v1 = ((const int4*)rows)[i1];
    if (p2) v2 = ((const int4*)rows)[i2];
    if (p3) v3 = ((const int4*)rows)[i3];
    if (p0) { atomicAdd(&g_deg[v0.x], 1); atomicAdd(&g_deg[v0.y], 1);
              atomicAdd(&g_deg[v0.z], 1); atomicAdd(&g_deg[v0.w], 1); }
    if (p1) { atomicAdd(&g_deg[v1.x], 1); atomicAdd(&g_deg[v1.y], 1);
              atomicAdd(&g_deg[v1.z], 1); atomicAdd(&g_deg[v1.w], 1); }
    if (p2) { atomicAdd(&g_deg[v2.x], 1); atomicAdd(&g_deg[v2.y], 1);
              atomicAdd(&g_deg[v2.z], 1); atomicAdd(&g_deg[v2.w], 1); }
    if (p3) { atomicAdd(&g_deg[v3.x], 1); atomicAdd(&g_deg[v3.y], 1);
              atomicAdd(&g_deg[v3.z], 1); atomicAdd(&g_deg[v3.w], 1); }
    // tail
    int j = nE4 * 4 + t;
    if (j < nE && t < nE - nE4 * 4) atomicAdd(&g_deg[rows[j]], 1);
}

// block-scan of degrees; also computes dinv (folded, saves a kernel)
__global__ __launch_bounds__(SCAN_B) void scanA_kernel() {
    __shared__ int s[SCAN_B];
    int tid = threadIdx.x;
    int i = blockIdx.x * SCAN_B + tid;
    int v = (i < N_NODES) ? g_deg[i] : 0;
    if (i < N_NODES) g_dinv[i] = rsqrtf((float)max(v, 1));
    s[tid] = v;
    __syncthreads();
#pragma unroll
    for (int off = 1; off < SCAN_B; off <<= 1) {
        int t = (tid >= off) ? s[tid - off] : 0;
        __syncthreads();
        s[tid] += t;
        __syncthreads();
    }
    if (i < N_NODES) g_rowptr[i] = s[tid] - v;
    if (tid == SCAN_B - 1) g_bsum[blockIdx.x] = s[tid];
}

__global__ void scanB_kernel(int nb) {
    __shared__ int s[128];
    int tid = threadIdx.x;
    int v = (tid < nb) ? g_bsum[tid] : 0;
    s[tid] = v;
    __syncthreads();
#pragma unroll
    for (int off = 1; off < 128; off <<= 1) {
        int t = (tid >= off) ? s[tid - off] : 0;
        __syncthreads();
        s[tid] += t;
        __syncthreads();
    }
    if (tid < nb) g_bsum[tid] = s[tid] - v;
}

__global__ __launch_bounds__(SCAN_B) void scanC_kernel(int nE) {
    int i = blockIdx.x * SCAN_B + threadIdx.x;
    if (i < N_NODES) {
        int rp = g_rowptr[i] + g_bsum[blockIdx.x];
        g_rowptr[i] = rp;
        g_cursor[i] = rp;
    }
    if (i == 0) g_rowptr[N_NODES] = nE;
}

__device__ __forceinline__ void scatter_one(int r, int c) {
    int pos = atomicAdd(&g_cursor[r], 1);
    float w = g_dinv[r] * g_dinv[c];
    g_edge[pos] = make_int2(c, __float_as_int(w));
}

__global__ void scatter_kernel(const int* __restrict__ rows, const int* __restrict__ cols,
                               int nE4, int nE) {
    int i = blockIdx.x * blockDim.x + threadIdx.x;
    if (i < nE4) {
        int4 r = ((const int4*)rows)[i];
        int4 c = ((const int4*)cols)[i];
        scatter_one(r.x, c.x);
        scatter_one(r.y, c.y);
        scatter_one(r.z, c.z);
        scatter_one(r.w, c.w);
    } else {
        int j = nE4 * 4 + (i - nE4);
        if (j < nE) scatter_one(rows[j], cols[j]);
    }
}

// split W2 (fp32 [128,64]) into transposed fp16 hi/lo planes [n][k]
__global__ void w2split_kernel(const float* __restrict__ W2) {
    int i = blockIdx.x * blockDim.x + threadIdx.x;
    if (i < 128 * 64) {
        int k = i / 64, n = i % 64;
        float v = W2[i];
        __half hi = __float2half_rn(v);
        float lo = v - __half2float(hi);
        g_W2T[0][n * 128 + k] = hi;
        g_W2T[1][n * 128 + k] = __float2half_rn(lo);
    }
}

// ---------------- GEMM1: XW1h = X @ W1 (fp32 in, tf32x3, fp16 out) ----------------
__global__ __launch_bounds__(256)
void mma_gemm1(int M, const float* __restrict__ A,
               const float* __restrict__ B, __half* __restrict__ C) {
    constexpr int BN = 128, BK = 32, K = 256, N = 128;
    constexpr int AS = 36;
    constexpr int BS = BN + 8;
    constexpr int A_STAGE = 128 * AS;
    constexpr int B_STAGE = BK * BS;
    constexpr int STAGE   = A_STAGE + B_STAGE;

    extern __shared__ float smem[];

    const int tid    = threadIdx.x;
    const int lane   = tid & 31;
    const int wid    = tid >> 5;
    const int warp_m = wid & 3;
    const int warp_n = wid >> 2;
    const int g      = lane >> 2;
    const int q      = lane & 3;
    const int rowBase = blockIdx.y * 128;

    float acc[2][8][4];
#pragma unroll
    for (int mt = 0; mt < 2; mt++)
#pragma unroll
        for (int nt = 0; nt < 8; nt++)
#pragma unroll
            for (int r = 0; r < 4; r++) acc[mt][nt][r] = 0.f;

    auto load_tile = [&](int stage, int k0) {
        float* sA = smem + stage * STAGE;
        float* sB = sA + A_STAGE;
#pragma unroll
        for (int i = 0; i < 4; i++) {
            int e = tid + i * 256;
            int r = e >> 3;
            int c4 = (e & 7) * 4;
            int gr = rowBase + r;
            cp_async16(sA + r * AS + c4, A + (size_t)gr * K + k0 + c4, gr < M);
        }
#pragma unroll
        for (int i = 0; i < 4; i++) {
            int e = tid + i * 256;
            int r = e >> 5;
            int c4 = (e & 31) * 4;
            cp_async16(sB + r * BS + c4, B + (size_t)(k0 + r) * N + c4, true);
        }
        asm volatile("cp.async.commit_group;" ::: "memory");
    };

    load_tile(0, 0);

    for (int it = 0; it < K / BK; ++it) {
        int cur = it & 1;
        if (it + 1 < K / BK) {
            load_tile(cur ^ 1, (it + 1) * BK);
            asm volatile("cp.async.wait_group 1;" ::: "memory");
        } else {
            asm volatile("cp.async.wait_group 0;" ::: "memory");
        }
        __syncthreads();

        const float* sA = smem + cur * STAGE;
        const float* sB = sA + A_STAGE;

#pragma unroll
        for (int ks = 0; ks < 4; ks++) {
            float ah[2][4], al[2][4];
#pragma unroll
            for (int mt = 0; mt < 2; mt++) {
                const float* ap = sA + (warp_m * 32 + mt * 16 + g) * AS + ks * 8 + q;
                float a0 = ap[0];
                float a1 = ap[8 * AS];
                float a2 = ap[4];
                float a3 = ap[8 * AS + 4];
                ah[mt][0] = tf32_rnd(a0); al[mt][0] = tf32_rnd(a0 - ah[mt][0]);
                ah[mt][1] = tf32_rnd(a1); al[mt][1] = tf32_rnd(a1 - ah[mt][1]);
                ah[mt][2] = tf32_rnd(a2); al[mt][2] = tf32_rnd(a2 - ah[mt][2]);
                ah[mt][3] = tf32_rnd(a3); al[mt][3] = tf32_rnd(a3 - ah[mt][3]);
            }
#pragma unroll
            for (int nt = 0; nt < 8; nt++) {
                const float* bp = sB + (ks * 8 + q) * BS + warp_n * 64 + nt * 8 + g;
                float b0 = bp[0];
                float b1 = bp[4 * BS];
                float bh[2], bl[2];
                bh[0] = tf32_rnd(b0); bl[0] = tf32_rnd(b0 - bh[0]);
                bh[1] = tf32_rnd(b1); bl[1] = tf32_rnd(b1 - bh[1]);
#pragma unroll
                for (int mt = 0; mt < 2; mt++) {
                    mma_tf32(acc[mt][nt], ah[mt], bh);
                    mma_tf32(acc[mt][nt], al[mt], bh);
                    mma_tf32(acc[mt][nt], ah[mt], bl);
                }
            }
        }
        __syncthreads();
    }

#pragma unroll
    for (int mt = 0; mt < 2; mt++) {
        int r0 = rowBase + warp_m * 32 + mt * 16 + g;
        int r1 = r0 + 8;
#pragma unroll
        for (int nt = 0; nt < 8; nt++) {
            int col = warp_n * 64 + nt * 8 + 2 * q;
            if (r0 < M)
                *(__half2*)(C + (size_t)r0 * N + col) = __floats2half2_rn(acc[mt][nt][0], acc[mt][nt][1]);
            if (r1 < M)
                *(__half2*)(C + (size_t)r1 * N + col) = __floats2half2_rn(acc[mt][nt][2], acc[mt][nt][3]);
        }
    }
}

// ---------------- GEMM2: HW2h = Hh @ W2 (fp16 HMMA, B = hi+lo planes) ----------------
// M x 64 x 128 in one shot: whole K in smem. 256 threads (8 warps 4x2).
__global__ __launch_bounds__(256)
void gemm2_f16(int M, const __half* __restrict__ A, __half* __restrict__ C) {
    constexpr int SA = 136;   // halves per A row (272 B, 16B-aligned, conflict-free)
    constexpr int SB = 136;
    extern __shared__ __half smh[];
    __half* sA  = smh;                 // 128 x SA
    __half* sBh = smh + 128 * SA;      // 64 x SB
    __half* sBl = sBh + 64 * SB;       // 64 x SB

    const int tid  = threadIdx.x;
    const int lane = tid & 31;
    const int wid  = tid >> 5;
    const int warp_m = wid & 3;
    const int warp_n = wid >> 2;
    const int g = lane >> 2;
    const int q = lane & 3;
    const int rowBase = blockIdx.x * 128;

    // A: 128 rows x 256B = 2048 x 16B chunks, 8 per thread
#pragma unroll
    for (int i = 0; i < 8; i++) {
        int e = tid + i * 256;
        int r = e >> 4;
        int c8 = (e & 15) * 8;
        int gr = rowBase + r;
        cp_async16(sA + r * SA + c8, A + (size_t)gr * 128 + c8, gr < M);
    }
    // B planes: 64 x 256B each = 1024 chunks, 4 per thread per plane
#pragma unroll
    for (int i = 0; i < 4; i++) {
        int e = tid + i * 256;
        int r = e >> 4;
        int c8 = (e & 15) * 8;
        cp_async16(sBh + r * SB + c8, g_W2T[0] + r * 128 + c8, true);
        cp_async16(sBl + r * SB + c8, g_W2T[1] + r * 128 + c8, true);
    }
    asm volatile("cp.async.commit_group;\n\tcp.async.wait_group 0;" ::: "memory");
    __syncthreads();

    float acc[2][4][4];
#pragma unroll
    for (int mt = 0; mt < 2; mt++)
#pragma unroll
        for (int nt = 0; nt < 4; nt++)
#pragma unroll
            for (int r = 0; r < 4; r++) acc[mt][nt][r] = 0.f;

#pragma unroll
    for (int ks = 0; ks < 8; ks++) {
        uint32_t a[2][4];
#pragma unroll
        for (int mt = 0; mt < 2; mt++) {
            const __half* ap = sA + (warp_m * 32 + mt * 16) * SA + ks * 16;
            a[mt][0] = *(const uint32_t*)(ap + (size_t)g * SA + 2 * q);
            a[mt][1] = *(const uint32_t*)(ap + (size_t)(g + 8) * SA + 2 * q);
            a[mt][2] = *(const uint32_t*)(ap + (size_t)g * SA + 2 * q + 8);
            a[mt][3] = *(const uint32_t*)(ap + (size_t)(g + 8) * SA + 2 * q + 8);
        }
#pragma unroll
        for (int nt = 0; nt < 4; nt++) {
            int c = warp_n * 32 + nt * 8 + g;
            uint32_t bh0 = *(const uint32_t*)(sBh + (size_t)c * SB + ks * 16 + 2 * q);
            uint32_t bh1 = *(const uint32_t*)(sBh + (size_t)c * SB + ks * 16 + 2 * q + 8);
            uint32_t bl0 = *(const uint32_t*)(sBl + (size_t)c * SB + ks * 16 + 2 * q);
            uint32_t bl1 = *(const uint32_t*)(sBl + (size_t)c * SB + ks * 16 + 2 * q + 8);
#pragma unroll
            for (int mt = 0; mt < 2; mt++) {
                mma_f16(acc[mt][nt], a[mt], bl0, bl1);
                mma_f16(acc[mt][nt], a[mt], bh0, bh1);
            }
        }
    }

#pragma unroll
    for (int mt = 0; mt < 2; mt++) {
        int r0 = rowBase + warp_m * 32 + mt * 16 + g;
        int r1 = r0 + 8;
#pragma unroll
        for (int nt = 0; nt < 4; nt++) {
            int col = warp_n * 32 + nt * 8 + 2 * q;
            if (r0 < M)
                *(__half2*)(C + (size_t)r0 * 64 + col) = __floats2half2_rn(acc[mt][nt][0], acc[mt][nt][1]);
            if (r1 < M)
                *(__half2*)(C + (size_t)r1 * 64 + col) = __floats2half2_rn(acc[mt][nt][2], acc[mt][nt][3]);
        }
    }
}

// ---------------- SPMM1 (fp16): Hh = relu(A_hat @ XW1h), width 128 ----------------
__global__ __launch_bounds__(256) void spmm_csr128h(const __half* __restrict__ src,
                                                    __half* __restrict__ dst) {
    int row = blockIdx.x * 8 + (threadIdx.x >> 5);
    if (row >= N_NODES) return;
    int lane = threadIdx.x & 31;
    int e   = g_rowptr[row];
    int end = g_rowptr[row + 1];

    float4 acc = make_float4(0.f, 0.f, 0.f, 0.f);
    for (; e + 3 < end; e += 4) {
        int2 e0 = g_edge[e];
        int2 e1 = g_edge[e + 1];
        int2 e2 = g_edge[e + 2];
        int2 e3 = g_edge[e + 3];
        uint2 r0 = ((const uint2*)(src + (size_t)e0.x * 128))[lane];
        uint2 r1 = ((const uint2*)(src + (size_t)e1.x * 128))[lane];
        uint2 r2 = ((const uint2*)(src + (size_t)e2.x * 128))[lane];
        uint2 r3 = ((const uint2*)(src + (size_t)e3.x * 128))[lane];
        float w0 = __int_as_float(e0.y), w1 = __int_as_float(e1.y);
        float w2 = __int_as_float(e2.y), w3 = __int_as_float(e3.y);
        float2 a0 = __half22float2(*(__half2*)&r0.x), b0 = __half22float2(*(__half2*)&r0.y);
        float2 a1 = __half22float2(*(__half2*)&r1.x), b1 = __half22float2(*(__half2*)&r1.y);
        float2 a2 = __half22float2(*(__half2*)&r2.x), b2 = __half22float2(*(__half2*)&r2.y);
        float2 a3 = __half22float2(*(__half2*)&r3.x), b3 = __half22float2(*(__half2*)&r3.y);
        acc.x += w0 * a0.x + w1 * a1.x + w2 * a2.x + w3 * a3.x;
        acc.y += w0 * a0.y + w1 * a1.y + w2 * a2.y + w3 * a3.y;
        acc.z += w0 * b0.x + w1 * b1.x + w2 * b2.x + w3 * b3.x;
        acc.w += w0 * b0.y + w1 * b1.y + w2 * b2.y + w3 * b3.y;
    }
    for (; e < end; e++) {
        int2 ed = g_edge[e];
        float w = __int_as_float(ed.y);
        uint2 r0 = ((const uint2*)(src + (size_t)ed.x * 128))[lane];
        float2 a0 = __half22float2(*(__half2*)&r0.x), b0 = __half22float2(*(__half2*)&r0.y);
        acc.x += w * a0.x; acc.y += w * a0.y;
        acc.z += w * b0.x; acc.w += w * b0.y;
    }
    uint2 outv;
    *(__half2*)&outv.x = __floats2half2_rn(fmaxf(acc.x, 0.f), fmaxf(acc.y, 0.f));
    *(__half2*)&outv.y = __floats2half2_rn(fmaxf(acc.z, 0.f), fmaxf(acc.w, 0.f));
    ((uint2*)(dst + (size_t)row * 128))[lane] = outv;
}

// ---------------- SPMM2 (fp16 in, fp32 out): out = A_hat @ HW2h, width 64 ----------------
__global__ __launch_bounds__(256) void spmm_csr64h(const __half* __restrict__ src,
                                                   float* __restrict__ dst) {
    int row = blockIdx.x * 8 + (threadIdx.x >> 5);
    if (row >= N_NODES) return;
    int lane = threadIdx.x & 31;
    int e   = g_rowptr[row];
    int end = g_rowptr[row + 1];

    float2 acc = make_float2(0.f, 0.f);
    for (; e + 3 < end; e += 4) {
        int2 e0 = g_edge[e];
        int2 e1 = g_edge[e + 1];
        int2 e2 = g_edge[e + 2];
        int2 e3 = g_edge[e + 3];
        __half2 h0 = ((const __half2*)(src + (size_t)e0.x * 64))[lane];
        __half2 h1 = ((const __half2*)(src + (size_t)e1.x * 64))[lane];
        __half2 h2 = ((const __half2*)(src + (size_t)e2.x * 64))[lane];
        __half2 h3 = ((const __half2*)(src + (size_t)e3.x * 64))[lane];
        float w0 = __int_as_float(e0.y), w1 = __int_as_float(e1.y);
        float w2 = __int_as_float(e2.y), w3 = __int_as_float(e3.y);
        float2 f0 = __half22float2(h0);
        float2 f1 = __half22float2(h1);
        float2 f2 = __half22float2(h2);
        float2 f3 = __half22float2(h3);
        acc.x += w0 * f0.x + w1 * f1.x + w2 * f2.x + w3 * f3.x;
        acc.y += w0 * f0.y + w1 * f1.y + w2 * f2.y + w3 * f3.y;
    }
    for (; e < end; e++) {
        int2 ed = g_edge[e];
        float w = __int_as_float(ed.y);
        float2 f = __half22float2(((const __half2*)(src + (size_t)ed.x * 64))[lane]);
        acc.x += w * f.x;
        acc.y += w * f.y;
    }
    ((float2*)(dst + (size_t)row * 64))[lane] = acc;
}

// ---------------- launch ----------------
extern "C" void kernel_launch(void* const* d_in, const int* in_sizes, int n_in,
                              void* d_out, int out_size) {
    const float* X  = (const float*)d_in[0];
    const float* W1 = (const float*)d_in[1];
    const float* W2 = (const float*)d_in[2];
    const int* er   = (const int*)d_in[3];
    const int* ec   = (const int*)d_in[4];
    float* out = (float*)d_out;

    const int M  = in_sizes[0] / 256;   // 100000
    const int nE = in_sizes[3];         // 1700000
    const int nE4 = nE / 4;

    __half *p_xw1, *p_h, *p_hw2;
    cudaGetSymbolAddress((void**)&p_xw1, g_XW1h);
    cudaGetSymbolAddress((void**)&p_h,   g_Hh);
    cudaGetSymbolAddress((void**)&p_hw2, g_HW2h);

    const int smem1 = 2 * (128 * 36 + 32 * (128 + 8)) * 4;             // 71680
    const int smem2 = (128 * 136 + 2 * 64 * 136) * (int)sizeof(__half); // 69632

    static cudaStream_t s_side = nullptr;
    static cudaEvent_t  ev_fork = nullptr, ev_join = nullptr;
    if (!s_side) {
        cudaStreamCreateWithFlags(&s_side, cudaStreamNonBlocking);
        cudaEventCreateWithFlags(&ev_fork, cudaEventDisableTiming);
        cudaEventCreateWithFlags(&ev_join, cudaEventDisableTiming);
        cudaFuncSetAttribute(mma_gemm1,
                             cudaFuncAttributeMaxDynamicSharedMemorySize, smem1);
        cudaFuncSetAttribute(gemm2_f16,
                             cudaFuncAttributeMaxDynamicSharedMemorySize, smem2);
    }

    // ---- fork: CSR build + W2 split on side stream, GEMM1 on main ----
    cudaEventRecord(ev_fork, 0);
    cudaStreamWaitEvent(s_side, ev_fork, 0);

    w2split_kernel<<<(128 * 64 + 255) / 256, 256, 0, s_side>>>(W2);
    zero_deg_kernel<<<(N_NODES + 255) / 256, 256, 0, s_side>>>();
    {
        int blocks = (nE4 + 4 * 256 - 1) / (4 * 256);
        deg_kernel<<<blocks, 256, 0, s_side>>>(er, nE4, nE);
    }
    scanA_kernel<<<NUM_SB, SCAN_B, 0, s_side>>>();
    scanB_kernel<<<1, 128, 0, s_side>>>(NUM_SB);
    scanC_kernel<<<NUM_SB, SCAN_B, 0, s_side>>>(nE);
    scatter_kernel<<<(nE4 + 3 + 255) / 256, 256, 0, s_side>>>(er, ec, nE4, nE);
    cudaEventRecord(ev_join, s_side);

    // main stream: GEMM1 (independent of CSR)
    {
        dim3 grid(1, (M + 127) / 128);
        mma_gemm1<<<grid, 256, smem1>>>(M, X, W1, p_xw1);
    }

    // ---- join ----
    cudaStreamWaitEvent(0, ev_join, 0);

    // SPMM1: Hh = relu(A_hat @ XW1h)
    spmm_csr128h<<<(N_NODES + 7) / 8, 256>>>(p_xw1, p_h);

    // GEMM2: HW2h = Hh @ W2 (fp16 HMMA)
    gemm2_f16<<<(M + 127) / 128, 256, smem2>>>(M, p_h, p_hw2);

    // SPMM2: out = A_hat @ HW2h
    spmm_csr64h<<<(N_NODES + 7) / 8, 256>>>(p_hw2, out);
}